// round 1
// baseline (speedup 1.0000x reference)
#include <cuda_runtime.h>
#include <math.h>

#define S_ 32
#define H_ 768
#define I_ 768
#define E_ 32
#define TOPK_ 4
#define LIMIT_ 7.0f
#define ALPHA_ 1.702f
#define EPS_ 1e-5f

// Scratch (device globals: allocation-free)
__device__ float g_t[S_ * H_];          // rmsnormed tokens
__device__ int   g_idx[S_ * TOPK_];     // top-k expert ids
__device__ float g_wts[S_ * TOPK_];     // softmax weights
__device__ int   g_cnt[E_];             // tokens per expert
__device__ int   g_sel[E_ * S_];        // sel = s*4+k per expert slot
__device__ float g_act[S_ * TOPK_ * I_]; // post-SwiGLU activations

// ---------------------------------------------------------------------------
// Kernel 1: RMSNorm + router (logits, top-4, softmax) + residual init
// grid = S_ blocks, 256 threads
// ---------------------------------------------------------------------------
__global__ void __launch_bounds__(256) k_norm_router(
    const float* __restrict__ x, const float* __restrict__ nscale,
    const float* __restrict__ gw, const float* __restrict__ gb,
    float* __restrict__ out)
{
    int s   = blockIdx.x;
    int tid = threadIdx.x;
    int lane = tid & 31, wid = tid >> 5;

    __shared__ float sh_t[H_];
    __shared__ float red[8];
    __shared__ float logits[E_];

    // load x row, sum of squares
    float v0[3];
    float ss = 0.f;
#pragma unroll
    for (int q = 0; q < 3; q++) {
        float v = x[s * H_ + tid + 256 * q];
        v0[q] = v;
        ss += v * v;
    }
#pragma unroll
    for (int o = 16; o; o >>= 1) ss += __shfl_xor_sync(0xffffffffu, ss, o);
    if (lane == 0) red[wid] = ss;
    __syncthreads();
    if (tid < 8) {
        float r = red[tid];
#pragma unroll
        for (int o = 4; o; o >>= 1) r += __shfl_xor_sync(0xffu, r, o);
        if (tid == 0) red[0] = r;
    }
    __syncthreads();
    float rms = rsqrtf(red[0] / (float)H_ + EPS_);

#pragma unroll
    for (int q = 0; q < 3; q++) {
        int j = tid + 256 * q;
        float t = v0[q] * rms * nscale[j];
        sh_t[j] = t;
        g_t[s * H_ + j] = t;
        out[s * H_ + j] = v0[q];   // residual init out = x
    }
    __syncthreads();

    // router logits: warp wid handles experts 4*wid .. 4*wid+3
#pragma unroll
    for (int e4 = 0; e4 < 4; e4++) {
        int e = wid * 4 + e4;
        float acc = 0.f;
        for (int j = lane; j < H_; j += 32) acc += sh_t[j] * gw[e * H_ + j];
#pragma unroll
        for (int o = 16; o; o >>= 1) acc += __shfl_xor_sync(0xffffffffu, acc, o);
        if (lane == 0) logits[e] = acc + gb[e];
    }
    __syncthreads();

    if (tid == 0) {
        float l[E_];
#pragma unroll
        for (int e = 0; e < E_; e++) l[e] = logits[e];
        float vals[TOPK_];
        int   ids[TOPK_];
#pragma unroll
        for (int k = 0; k < TOPK_; k++) {
            float m = -1e30f; int mi = 0;
            for (int e = 0; e < E_; e++) {
                if (l[e] > m) { m = l[e]; mi = e; }
            }
            vals[k] = m; ids[k] = mi; l[mi] = -1e30f;
        }
        float mx = vals[0], sum = 0.f, w[TOPK_];
#pragma unroll
        for (int k = 0; k < TOPK_; k++) { w[k] = __expf(vals[k] - mx); sum += w[k]; }
        float inv = 1.f / sum;
#pragma unroll
        for (int k = 0; k < TOPK_; k++) {
            g_idx[s * TOPK_ + k] = ids[k];
            g_wts[s * TOPK_ + k] = w[k] * inv;
        }
    }
}

// ---------------------------------------------------------------------------
// Kernel 2: build per-expert selection lists (deterministic, single thread)
// ---------------------------------------------------------------------------
__global__ void k_build()
{
    if (threadIdx.x == 0 && blockIdx.x == 0) {
        for (int e = 0; e < E_; e++) g_cnt[e] = 0;
        for (int sel = 0; sel < S_ * TOPK_; sel++) {
            int e = g_idx[sel];
            g_sel[e * S_ + g_cnt[e]] = sel;
            g_cnt[e]++;
        }
    }
}

// ---------------------------------------------------------------------------
// Kernel 3: expert MLP-1 + interleaved SwiGLU (clamped)
// grid (12, E_), 256 threads; each block: 64 act outputs (128 w1 rows)
// ---------------------------------------------------------------------------
#define T1C 64
__global__ void __launch_bounds__(256) k_mlp1(
    const float* __restrict__ w1, const float* __restrict__ b1)
{
    int e = blockIdx.y;
    int n = g_cnt[e];
    if (n == 0) return;

    extern __shared__ float sm[];     // n * H_ floats of t
    __shared__ int ssel[S_];

    int tid = threadIdx.x, wid = tid >> 5, lane = tid & 31;

    if (tid < n) ssel[tid] = g_sel[e * S_ + tid];
    __syncthreads();

    for (int i = 0; i < n; i++) {
        int s = ssel[i] >> 2;
        for (int j = tid; j < H_; j += 256) sm[i * H_ + j] = g_t[s * H_ + j];
    }
    __syncthreads();

    int cbase = blockIdx.x * T1C;
    for (int c = cbase + wid; c < cbase + T1C; c += 8) {
        const float4* rg = (const float4*)(w1 + ((size_t)e * 2 * I_ + 2 * c) * H_);
        const float4* rl = rg + (H_ / 4);
        float4 wg[6], wl[6];
#pragma unroll
        for (int q = 0; q < 6; q++) {
            wg[q] = rg[lane + 32 * q];
            wl[q] = rl[lane + 32 * q];
        }
        for (int i = 0; i < n; i++) {
            const float4* tt = (const float4*)(sm + i * H_);
            float ag = 0.f, al = 0.f;
#pragma unroll
            for (int q = 0; q < 6; q++) {
                float4 tv = tt[lane + 32 * q];
                ag += wg[q].x * tv.x + wg[q].y * tv.y + wg[q].z * tv.z + wg[q].w * tv.w;
                al += wl[q].x * tv.x + wl[q].y * tv.y + wl[q].z * tv.z + wl[q].w * tv.w;
            }
#pragma unroll
            for (int o = 16; o; o >>= 1) {
                ag += __shfl_xor_sync(0xffffffffu, ag, o);
                al += __shfl_xor_sync(0xffffffffu, al, o);
            }
            if (lane == 0) {
                float hg = ag + b1[e * 2 * I_ + 2 * c];
                float hl = al + b1[e * 2 * I_ + 2 * c + 1];
                hg = fminf(hg, LIMIT_);
                hl = fminf(fmaxf(hl, -LIMIT_), LIMIT_);
                float sig = 1.f / (1.f + __expf(-ALPHA_ * hg));
                g_act[ssel[i] * I_ + c] = hg * sig * (hl + 1.f);
            }
        }
    }
}

// ---------------------------------------------------------------------------
// Kernel 4: expert MLP-2 + weighted accumulation into out
// grid (12, E_), 256 threads; each block: 64 output rows of H
// ---------------------------------------------------------------------------
#define T2C 64
__global__ void __launch_bounds__(256) k_mlp2(
    const float* __restrict__ w2, const float* __restrict__ b2,
    float* __restrict__ out)
{
    int e = blockIdx.y;
    int n = g_cnt[e];
    if (n == 0) return;

    extern __shared__ float sm[];     // n * I_ floats of act
    __shared__ int   ssel[S_];
    __shared__ float swt[S_];

    int tid = threadIdx.x, wid = tid >> 5, lane = tid & 31;

    if (tid < n) {
        int sel = g_sel[e * S_ + tid];
        ssel[tid] = sel;
        swt[tid]  = g_wts[sel];
    }
    __syncthreads();

    for (int i = 0; i < n; i++) {
        int sel = ssel[i];
        for (int j = tid; j < I_; j += 256) sm[i * I_ + j] = g_act[sel * I_ + j];
    }
    __syncthreads();

    int cbase = blockIdx.x * T2C;
    for (int c = cbase + wid; c < cbase + T2C; c += 8) {
        const float4* r = (const float4*)(w2 + ((size_t)e * H_ + c) * I_);
        float4 wv[6];
#pragma unroll
        for (int q = 0; q < 6; q++) wv[q] = r[lane + 32 * q];
        for (int i = 0; i < n; i++) {
            const float4* av = (const float4*)(sm + i * I_);
            float acc = 0.f;
#pragma unroll
            for (int q = 0; q < 6; q++) {
                float4 a = av[lane + 32 * q];
                acc += wv[q].x * a.x + wv[q].y * a.y + wv[q].z * a.z + wv[q].w * a.w;
            }
#pragma unroll
            for (int o = 16; o; o >>= 1) acc += __shfl_xor_sync(0xffffffffu, acc, o);
            if (lane == 0) {
                float val = acc + b2[e * H_ + c];
                int s = ssel[i] >> 2;
                atomicAdd(&out[s * H_ + c], swt[i] * val);
            }
        }
    }
}

// ---------------------------------------------------------------------------
extern "C" void kernel_launch(void* const* d_in, const int* in_sizes, int n_in,
                              void* d_out, int out_size)
{
    const float* x  = (const float*)d_in[0];
    const float* ns = (const float*)d_in[1];
    const float* gw = (const float*)d_in[2];
    const float* gb = (const float*)d_in[3];
    const float* w1 = (const float*)d_in[4];
    const float* b1 = (const float*)d_in[5];
    const float* w2 = (const float*)d_in[6];
    const float* b2 = (const float*)d_in[7];
    float* out = (float*)d_out;

    const int smem = S_ * H_ * sizeof(float);   // 98304 bytes (worst case n = 32)
    cudaFuncSetAttribute(k_mlp1, cudaFuncAttributeMaxDynamicSharedMemorySize, smem);
    cudaFuncSetAttribute(k_mlp2, cudaFuncAttributeMaxDynamicSharedMemorySize, smem);

    k_norm_router<<<S_, 256>>>(x, ns, gw, gb, out);
    k_build<<<1, 32>>>();
    dim3 g1(I_ / T1C, E_);   // (12, 32)
    k_mlp1<<<g1, 256, smem>>>(w1, b1);
    dim3 g2(H_ / T2C, E_);   // (12, 32)
    k_mlp2<<<g2, 256, smem>>>(w2, b2, out);
}

// round 2
// speedup vs baseline: 1.2802x; 1.2802x over previous
#include <cuda_runtime.h>
#include <math.h>

#define S_ 32
#define H_ 768
#define I_ 768
#define E_ 32
#define TOPK_ 4
#define LIMIT_ 7.0f
#define ALPHA_ 1.702f
#define EPS_ 1e-5f

#define TB 8           // max tokens per work chunk
#define MAXW 64        // max work chunks (true worst case is 44)

// Scratch (device globals: allocation-free)
__device__ float g_t[S_ * H_];           // rmsnormed tokens
__device__ int   g_idx[S_ * TOPK_];      // top-k expert ids
__device__ float g_wts[S_ * TOPK_];      // softmax weights
__device__ int   g_cnt[E_];              // tokens per expert
__device__ int   g_sel[E_ * S_];         // sel = s*4+k per expert slot
__device__ float g_act[S_ * TOPK_ * I_]; // post-SwiGLU activations
__device__ int   g_work[MAXW * 3];       // (expert, base, len)
__device__ int   g_nw;

// ---------------------------------------------------------------------------
// Kernel 1: RMSNorm + router (logits, top-4, softmax) + residual init
// ---------------------------------------------------------------------------
__global__ void __launch_bounds__(256) k_norm_router(
    const float* __restrict__ x, const float* __restrict__ nscale,
    const float* __restrict__ gw, const float* __restrict__ gb,
    float* __restrict__ out)
{
    int s   = blockIdx.x;
    int tid = threadIdx.x;
    int lane = tid & 31, wid = tid >> 5;

    __shared__ float sh_t[H_];
    __shared__ float red[8];
    __shared__ float logits[E_];

    float v0[3];
    float ss = 0.f;
#pragma unroll
    for (int q = 0; q < 3; q++) {
        float v = x[s * H_ + tid + 256 * q];
        v0[q] = v;
        ss += v * v;
    }
#pragma unroll
    for (int o = 16; o; o >>= 1) ss += __shfl_xor_sync(0xffffffffu, ss, o);
    if (lane == 0) red[wid] = ss;
    __syncthreads();
    if (tid < 8) {
        float r = red[tid];
#pragma unroll
        for (int o = 4; o; o >>= 1) r += __shfl_xor_sync(0xffu, r, o);
        if (tid == 0) red[0] = r;
    }
    __syncthreads();
    float rms = rsqrtf(red[0] / (float)H_ + EPS_);

#pragma unroll
    for (int q = 0; q < 3; q++) {
        int j = tid + 256 * q;
        float t = v0[q] * rms * nscale[j];
        sh_t[j] = t;
        g_t[s * H_ + j] = t;
        out[s * H_ + j] = v0[q];   // residual init out = x
    }
    __syncthreads();

#pragma unroll
    for (int e4 = 0; e4 < 4; e4++) {
        int e = wid * 4 + e4;
        float acc = 0.f;
        for (int j = lane; j < H_; j += 32) acc += sh_t[j] * gw[e * H_ + j];
#pragma unroll
        for (int o = 16; o; o >>= 1) acc += __shfl_xor_sync(0xffffffffu, acc, o);
        if (lane == 0) logits[e] = acc + gb[e];
    }
    __syncthreads();

    if (tid == 0) {
        float l[E_];
#pragma unroll
        for (int e = 0; e < E_; e++) l[e] = logits[e];
        float vals[TOPK_];
        int   ids[TOPK_];
#pragma unroll
        for (int k = 0; k < TOPK_; k++) {
            float m = -1e30f; int mi = 0;
            for (int e = 0; e < E_; e++) {
                if (l[e] > m) { m = l[e]; mi = e; }
            }
            vals[k] = m; ids[k] = mi; l[mi] = -1e30f;
        }
        float mx = vals[0], sum = 0.f, w[TOPK_];
#pragma unroll
        for (int k = 0; k < TOPK_; k++) { w[k] = __expf(vals[k] - mx); sum += w[k]; }
        float inv = 1.f / sum;
#pragma unroll
        for (int k = 0; k < TOPK_; k++) {
            g_idx[s * TOPK_ + k] = ids[k];
            g_wts[s * TOPK_ + k] = w[k] * inv;
        }
    }
}

// ---------------------------------------------------------------------------
// Kernel 2: build per-expert selection lists + work chunks (single thread)
// ---------------------------------------------------------------------------
__global__ void k_build()
{
    if (threadIdx.x == 0 && blockIdx.x == 0) {
        for (int e = 0; e < E_; e++) g_cnt[e] = 0;
        for (int sel = 0; sel < S_ * TOPK_; sel++) {
            int e = g_idx[sel];
            g_sel[e * S_ + g_cnt[e]] = sel;
            g_cnt[e]++;
        }
        int w = 0;
        for (int e = 0; e < E_; e++) {
            int n = g_cnt[e];
            for (int base = 0; base < n; base += TB) {
                int len = n - base; if (len > TB) len = TB;
                g_work[w * 3 + 0] = e;
                g_work[w * 3 + 1] = base;
                g_work[w * 3 + 2] = len;
                w++;
            }
        }
        g_nw = w;
    }
}

// ---------------------------------------------------------------------------
// Kernel 3: expert MLP-1 + interleaved SwiGLU (clamped)
// grid (I_/T1C, MAXW), 256 threads; block: T1C act outputs, <=TB tokens
// ---------------------------------------------------------------------------
#define T1C 32
__global__ void __launch_bounds__(256) k_mlp1(
    const float* __restrict__ w1, const float* __restrict__ b1)
{
    int widx = blockIdx.y;
    if (widx >= g_nw) return;
    int e    = g_work[widx * 3 + 0];
    int base = g_work[widx * 3 + 1];
    int n    = g_work[widx * 3 + 2];

    __shared__ float sm[TB * H_];     // 24 KB
    __shared__ int ssel[TB];

    int tid = threadIdx.x, wid = tid >> 5, lane = tid & 31;

    if (tid < n) ssel[tid] = g_sel[e * S_ + base + tid];
    __syncthreads();

    for (int i = 0; i < n; i++) {
        int s = ssel[i] >> 2;
        for (int j = tid; j < H_; j += 256) sm[i * H_ + j] = g_t[s * H_ + j];
    }
    __syncthreads();

    int cbase = blockIdx.x * T1C;
#pragma unroll
    for (int jj = 0; jj < T1C / 8; jj++) {
        int c = cbase + wid + 8 * jj;
        const float4* rg = (const float4*)(w1 + ((size_t)e * 2 * I_ + 2 * c) * H_);
        const float4* rl = rg + (H_ / 4);
        float4 wg[6], wl[6];
#pragma unroll
        for (int q = 0; q < 6; q++) {
            wg[q] = rg[lane + 32 * q];
            wl[q] = rl[lane + 32 * q];
        }
        for (int i = 0; i < n; i++) {
            const float4* tt = (const float4*)(sm + i * H_);
            float ag = 0.f, al = 0.f, ag2 = 0.f, al2 = 0.f;
#pragma unroll
            for (int q = 0; q < 6; q += 2) {
                float4 tv = tt[lane + 32 * q];
                float4 tv2 = tt[lane + 32 * (q + 1)];
                ag  += wg[q].x * tv.x + wg[q].y * tv.y + wg[q].z * tv.z + wg[q].w * tv.w;
                al  += wl[q].x * tv.x + wl[q].y * tv.y + wl[q].z * tv.z + wl[q].w * tv.w;
                ag2 += wg[q+1].x * tv2.x + wg[q+1].y * tv2.y + wg[q+1].z * tv2.z + wg[q+1].w * tv2.w;
                al2 += wl[q+1].x * tv2.x + wl[q+1].y * tv2.y + wl[q+1].z * tv2.z + wl[q+1].w * tv2.w;
            }
            ag += ag2; al += al2;
#pragma unroll
            for (int o = 16; o; o >>= 1) {
                ag += __shfl_xor_sync(0xffffffffu, ag, o);
                al += __shfl_xor_sync(0xffffffffu, al, o);
            }
            if (lane == 0) {
                float hg = ag + b1[e * 2 * I_ + 2 * c];
                float hl = al + b1[e * 2 * I_ + 2 * c + 1];
                hg = fminf(hg, LIMIT_);
                hl = fminf(fmaxf(hl, -LIMIT_), LIMIT_);
                float sig = 1.f / (1.f + __expf(-ALPHA_ * hg));
                g_act[ssel[i] * I_ + c] = hg * sig * (hl + 1.f);
            }
        }
    }
}

// ---------------------------------------------------------------------------
// Kernel 4: expert MLP-2 + weighted accumulation into out
// grid (H_/T2C, MAXW), 256 threads
// ---------------------------------------------------------------------------
#define T2C 32
__global__ void __launch_bounds__(256) k_mlp2(
    const float* __restrict__ w2, const float* __restrict__ b2,
    float* __restrict__ out)
{
    int widx = blockIdx.y;
    if (widx >= g_nw) return;
    int e    = g_work[widx * 3 + 0];
    int base = g_work[widx * 3 + 1];
    int n    = g_work[widx * 3 + 2];

    __shared__ float sm[TB * I_];     // 24 KB
    __shared__ int   ssel[TB];
    __shared__ float swt[TB];

    int tid = threadIdx.x, wid = tid >> 5, lane = tid & 31;

    if (tid < n) {
        int sel = g_sel[e * S_ + base + tid];
        ssel[tid] = sel;
        swt[tid]  = g_wts[sel];
    }
    __syncthreads();

    for (int i = 0; i < n; i++) {
        int sel = ssel[i];
        for (int j = tid; j < I_; j += 256) sm[i * I_ + j] = g_act[sel * I_ + j];
    }
    __syncthreads();

    int cbase = blockIdx.x * T2C;
#pragma unroll
    for (int jj = 0; jj < T2C / 8; jj++) {
        int c = cbase + wid + 8 * jj;
        const float4* r = (const float4*)(w2 + ((size_t)e * H_ + c) * I_);
        float4 wv[6];
#pragma unroll
        for (int q = 0; q < 6; q++) wv[q] = r[lane + 32 * q];
        for (int i = 0; i < n; i++) {
            const float4* av = (const float4*)(sm + i * I_);
            float acc = 0.f, acc2 = 0.f;
#pragma unroll
            for (int q = 0; q < 6; q += 2) {
                float4 a  = av[lane + 32 * q];
                float4 a2 = av[lane + 32 * (q + 1)];
                acc  += wv[q].x * a.x + wv[q].y * a.y + wv[q].z * a.z + wv[q].w * a.w;
                acc2 += wv[q+1].x * a2.x + wv[q+1].y * a2.y + wv[q+1].z * a2.z + wv[q+1].w * a2.w;
            }
            acc += acc2;
#pragma unroll
            for (int o = 16; o; o >>= 1) acc += __shfl_xor_sync(0xffffffffu, acc, o);
            if (lane == 0) {
                float val = acc + b2[e * H_ + c];
                int s = ssel[i] >> 2;
                atomicAdd(&out[s * H_ + c], swt[i] * val);
            }
        }
    }
}

// ---------------------------------------------------------------------------
extern "C" void kernel_launch(void* const* d_in, const int* in_sizes, int n_in,
                              void* d_out, int out_size)
{
    const float* x  = (const float*)d_in[0];
    const float* ns = (const float*)d_in[1];
    const float* gw = (const float*)d_in[2];
    const float* gb = (const float*)d_in[3];
    const float* w1 = (const float*)d_in[4];
    const float* b1 = (const float*)d_in[5];
    const float* w2 = (const float*)d_in[6];
    const float* b2 = (const float*)d_in[7];
    float* out = (float*)d_out;

    k_norm_router<<<S_, 256>>>(x, ns, gw, gb, out);
    k_build<<<1, 32>>>();
    dim3 g1(I_ / T1C, MAXW);   // (24, 64)
    k_mlp1<<<g1, 256>>>(w1, b1);
    dim3 g2(H_ / T2C, MAXW);   // (24, 64)
    k_mlp2<<<g2, 256>>>(w2, b2, out);
}